// round 13
// baseline (speedup 1.0000x reference)
#include <cuda_runtime.h>
#include <math.h>

// Quincunx lattice max pooling, shapes fixed by the problem:
//   coset0, coset1: [B=4, C=32, H=512, W=512] fp32
//   out:            [2, B, C, H, W] fp32   (out0 then out1)
//
// out0[i,j] = max(c0[i,j], c0[i+1,j], c0[i,j+1], c0[i+1,j+1], c1[i,j])
// out1[i,j] = max(c1[i,j], c1[i+1,j], c1[i,j+1], c1[i+1,j+1], c0[i+1,j+1])
// OOB -> -inf (ignored).
//
// R11: Blackwell 256-bit loads (ld.global.nc.v8.f32 -> LDG.E.256).
// Unit = 2 output rows x 8 columns x both cosets; 6x 256-bit loads/thread.
// Horizontal neighbor of the low float4 is in-thread; only the high half
// needs the lane+1 shuffle (half the shuffles of R9). __stwt stores.
// Exact grid (4096 x 512) -> no bounds check. p is warp-uniform so the
// last_pair branch never diverges.

#define HH   512
#define WW   512
#define W8   64           // 8-float groups per row
#define PP   256          // row pairs per image
#define NEGINF __int_as_float(0xff800000)

#define LDG256(d, p) asm volatile( \
    "ld.global.nc.v8.f32 {%0,%1,%2,%3,%4,%5,%6,%7}, [%8];" \
    : "=f"((d)[0]), "=f"((d)[1]), "=f"((d)[2]), "=f"((d)[3]), \
      "=f"((d)[4]), "=f"((d)[5]), "=f"((d)[6]), "=f"((d)[7]) \
    : "l"(p))

__global__ void __launch_bounds__(512)
lattice_pool_kernel(const float* __restrict__ c0,
                    const float* __restrict__ c1,
                    float* __restrict__ out0,
                    float* __restrict__ out1)
{
    int idx = blockIdx.x * 512 + threadIdx.x;

    int jv  = idx & (W8 - 1);           // 8-col group
    int p   = (idx >> 6) & (PP - 1);    // row pair (warp-uniform)
    long img = idx >> 14;               // (b,c) plane

    long base = img * (long)(HH * WW) + (long)(2 * p) * WW + (long)jv * 8;
    bool last_pair = (p == PP - 1);
    bool last_col  = (jv == W8 - 1);
    const float ni = NEGINF;

    // Rows 2p, 2p+1, 2p+2 of both cosets, 8 floats each.
    float A[3][8], B[3][8];
    LDG256(A[0], c0 + base);
    LDG256(A[1], c0 + base + WW);
    LDG256(B[0], c1 + base);
    LDG256(B[1], c1 + base + WW);
    if (!last_pair) {                    // warp-uniform branch
        LDG256(A[2], c0 + base + 2 * WW);
        LDG256(B[2], c1 + base + 2 * WW);
    } else {
#pragma unroll
        for (int k = 0; k < 8; k++) { A[2][k] = ni; B[2][k] = ni; }
    }

    // Horizontal tail (column 8*jv+8) = lane+1's element 0.
    const unsigned m = 0xffffffffu;
    float An[3], Bn[3];
#pragma unroll
    for (int r = 0; r < 3; r++) {
        An[r] = __shfl_down_sync(m, A[r][0], 1);
        Bn[r] = __shfl_down_sync(m, B[r][0], 1);
    }

    int lane = threadIdx.x & 31;
    if (lane == 31) {
        if (!last_col) {
            long e = base + 8;
            An[0] = __ldg(c0 + e);
            An[1] = __ldg(c0 + e + WW);
            Bn[0] = __ldg(c1 + e);
            Bn[1] = __ldg(c1 + e + WW);
            if (!last_pair) {
                An[2] = __ldg(c0 + e + 2 * WW);
                Bn[2] = __ldg(c1 + e + 2 * WW);
            } else {
                An[2] = ni; Bn[2] = ni;
            }
        } else {
#pragma unroll
            for (int r = 0; r < 3; r++) { An[r] = ni; Bn[r] = ni; }
        }
    }

    // Output rows r = 0,1 (global rows 2p+r), window rows (r, r+1).
#pragma unroll
    for (int r = 0; r < 2; r++) {
        float va[9], vb[9];
#pragma unroll
        for (int k = 0; k < 8; k++) {
            va[k] = fmaxf(A[r][k], A[r + 1][k]);
            vb[k] = fmaxf(B[r][k], B[r + 1][k]);
        }
        va[8] = fmaxf(An[r], An[r + 1]);
        vb[8] = fmaxf(Bn[r], Bn[r + 1]);

        float o0[8], o1[8];
#pragma unroll
        for (int k = 0; k < 8; k++) {
            o0[k] = fmaxf(fmaxf(va[k], va[k + 1]), B[r][k]);
            float adiag = (k < 7) ? A[r + 1][k + 1] : An[r + 1];
            o1[k] = fmaxf(fmaxf(vb[k], vb[k + 1]), adiag);
        }

        long ob = base + (long)r * WW;
        __stwt((float4*)(out0 + ob),     make_float4(o0[0], o0[1], o0[2], o0[3]));
        __stwt((float4*)(out0 + ob + 4), make_float4(o0[4], o0[5], o0[6], o0[7]));
        __stwt((float4*)(out1 + ob),     make_float4(o1[0], o1[1], o1[2], o1[3]));
        __stwt((float4*)(out1 + ob + 4), make_float4(o1[4], o1[5], o1[6], o1[7]));
    }
}

extern "C" void kernel_launch(void* const* d_in, const int* in_sizes, int n_in,
                              void* d_out, int out_size)
{
    const float* c0 = (const float*)d_in[0];
    const float* c1 = (const float*)d_in[1];
    long per_coset = in_sizes[0];              // floats per coset
    float* out0 = (float*)d_out;
    float* out1 = out0 + per_coset;

    // units of (2 rows x 8 cols): per_coset / 16 threads, exact multiple of 512
    int total = (int)(per_coset / 16);
    lattice_pool_kernel<<<total / 512, 512>>>(c0, c1, out0, out1);
}